// round 1
// baseline (speedup 1.0000x reference)
#include <cuda_runtime.h>
#include <cstdint>

#define BATCH 32
#define NBOX 25200
#define NCLS 80
#define MAXB 100
#define SCORE_T 0.25f
#define IOU_T 0.5f

#define CAP 4096      // candidate capacity (sorted)
#define TARGET 2048   // aim for this many candidates above cut
#define NBINS 4096
#define CHUNK 512

// scratch: scores for all boxes (allocation-free rule -> __device__ global)
__device__ float g_scores[BATCH * NBOX];

// ---------------------------------------------------------------------------
// Kernel A: score[i] = p[i] * (float)argmax_c(logits[i, c])
// memory-bound: streams 258MB of logits.
// ---------------------------------------------------------------------------
__global__ void score_kernel(const float* __restrict__ p,
                             const float* __restrict__ c,
                             float* __restrict__ scores) {
    int i = blockIdx.x * blockDim.x + threadIdx.x;
    if (i >= BATCH * NBOX) return;
    const float4* row = reinterpret_cast<const float4*>(c + (size_t)i * NCLS);
    float best = -3.402823e38f;
    int bidx = 0;
    #pragma unroll
    for (int q = 0; q < NCLS / 4; q++) {
        float4 v = row[q];
        if (v.x > best) { best = v.x; bidx = q * 4 + 0; }
        if (v.y > best) { best = v.y; bidx = q * 4 + 1; }
        if (v.z > best) { best = v.z; bidx = q * 4 + 2; }
        if (v.w > best) { best = v.w; bidx = q * 4 + 3; }
    }
    scores[i] = p[i] * (float)bidx;
}

// ---------------------------------------------------------------------------
// Kernel B: one CTA per batch.
//   1) histogram scores > SCORE_T into 4096 bins over [0.25, 80)
//   2) find bin cut so that >= TARGET candidates survive (capped at CAP)
//   3) compact (score,idx) as sortable u64 keys into SMEM
//   4) bitonic sort (score desc, idx asc)  -- exact argmax order incl. ties
//   5) warp-0 serial scan: accept iff IoU <= 0.5 vs all accepted so far
// ---------------------------------------------------------------------------
__global__ void __launch_bounds__(1024, 1)
nms_kernel(const float* __restrict__ boxes,
           const float* __restrict__ scores,
           float* __restrict__ out, int out_size) {
    __shared__ unsigned long long s_key[CAP];   // 32KB; first 16KB aliased as hist
    __shared__ float4 s_box[CHUNK];             // 8KB
    __shared__ float  s_cs[CHUNK];              // 2KB
    __shared__ float4 s_sel[MAXB];              // 1.6KB
    __shared__ int s_cnt, s_cutbin, s_C, s_nsel;
    __shared__ unsigned int s_wsum[32];

    const int b = blockIdx.x;
    const int tid = threadIdx.x;
    const int wid = tid >> 5, lane = tid & 31;
    const float* sc = scores + (size_t)b * NBOX;
    const float4* bx = reinterpret_cast<const float4*>(boxes) + (size_t)b * NBOX;
    float* pred = out + (size_t)b * MAXB * 6;

    // zero-fill this batch's prediction rows (d_out is poisoned)
    for (int i = tid; i < MAXB * 6; i += 1024) pred[i] = 0.0f;

    // --- Phase 1: histogram ---
    unsigned int* hist = reinterpret_cast<unsigned int*>(s_key);
    for (int i = tid; i < NBINS; i += 1024) hist[i] = 0u;
    if (tid == 0) { s_cnt = 0; s_nsel = 0; }
    __syncthreads();

    const float inv_w = (float)NBINS / (80.0f - SCORE_T);
    for (int i = tid; i < NBOX; i += 1024) {
        float s = sc[i];
        if (s > SCORE_T) {
            int bin = (int)((s - SCORE_T) * inv_w);
            bin = min(max(bin, 0), NBINS - 1);
            atomicAdd(&hist[bin], 1u);
        }
    }
    __syncthreads();

    // --- Phase 2: find cut bin (suffix count >= TARGET) ---
    {
        int base = wid * 128 + lane * 4;
        unsigned int w = hist[base] + hist[base + 1] + hist[base + 2] + hist[base + 3];
        #pragma unroll
        for (int o = 16; o; o >>= 1) w += __shfl_down_sync(0xffffffffu, w, o);
        if (lane == 0) s_wsum[wid] = w;
    }
    __syncthreads();
    if (tid == 0) {
        int acc = 0, cutbin = 0, C = 0, w;
        for (w = 31; w >= 0; w--) {
            if (acc + (int)s_wsum[w] >= TARGET) break;
            acc += (int)s_wsum[w];
        }
        if (w < 0) {                 // fewer than TARGET candidates total
            cutbin = 0; C = acc;
        } else {
            int bin;
            for (bin = w * 128 + 127; bin >= w * 128; bin--) {
                acc += (int)hist[bin];
                if (acc >= TARGET) break;
            }
            if (bin < w * 128) bin = w * 128;
            cutbin = bin; C = acc;
            if (C > CAP) {           // dense cut bin: step up one bin
                C -= (int)hist[cutbin];
                cutbin += 1;
            }
        }
        s_cutbin = cutbin; s_C = C;
    }
    __syncthreads();
    const int cutbin = s_cutbin;
    const int C = s_C;

    // --- Phase 3: compact (hist no longer read; keys alias it safely) ---
    for (int i = tid; i < NBOX; i += 1024) {
        float s = sc[i];
        if (s > SCORE_T) {
            int bin = (int)((s - SCORE_T) * inv_w);
            bin = min(max(bin, 0), NBINS - 1);
            if (bin >= cutbin) {
                int pos = atomicAdd(&s_cnt, 1);
                unsigned int sb = __float_as_uint(s);   // s > 0 => monotone bits
                s_key[pos] = ((unsigned long long)(~sb) << 32) | (unsigned int)i;
            }
        }
    }
    __syncthreads();
    for (int i = C + tid; i < CAP; i += 1024) s_key[i] = 0xFFFFFFFFFFFFFFFFULL;
    __syncthreads();

    // --- Phase 4: bitonic sort ascending (=> score desc, idx asc) ---
    for (int k = 2; k <= CAP; k <<= 1) {
        for (int j = k >> 1; j > 0; j >>= 1) {
            for (int t = tid; t < CAP; t += 1024) {
                int l = t ^ j;
                if (l > t) {
                    unsigned long long a = s_key[t], bb = s_key[l];
                    bool up = ((t & k) == 0);
                    if ((a > bb) == up) { s_key[t] = bb; s_key[l] = a; }
                }
            }
            __syncthreads();
        }
    }

    // --- Phase 5: chunked prefetch + warp-0 serial greedy scan ---
    int nsel = 0;
    for (int base = 0; base < C; base += CHUNK) {
        int n = min(CHUNK, C - base);
        for (int t = tid; t < n; t += 1024) {
            unsigned long long key = s_key[base + t];
            int idx = (int)(unsigned int)(key & 0xFFFFFFFFu);
            unsigned int sb = ~(unsigned int)(key >> 32);
            s_box[t] = bx[idx];
            s_cs[t] = __uint_as_float(sb);
        }
        __syncthreads();
        nsel = s_nsel;
        if (wid == 0) {
            for (int j = 0; j < n && nsel < MAXB; j++) {
                float4 cb = s_box[j];
                bool conflict = false;
                for (int k = lane; k < nsel; k += 32) {
                    float4 sb2 = s_sel[k];
                    // box layout: .x=y1 .y=x1 .z=y2 .w=x2 (reference order)
                    float iy = fmaxf(0.0f, fminf(sb2.z, cb.z) - fmaxf(sb2.x, cb.x));
                    float ix = fmaxf(0.0f, fminf(sb2.w, cb.w) - fmaxf(sb2.y, cb.y));
                    float inter = iy * ix;
                    float area_s = (sb2.z - sb2.x) * (sb2.w - sb2.y); // selected (= "b" in ref)
                    float area_c = (cb.z - cb.x) * (cb.w - cb.y);
                    float uni = (area_s + area_c) - inter;            // ref add order
                    float iou = (uni > 0.0f) ? inter / uni : 0.0f;
                    if (iou > IOU_T) conflict = true;
                }
                unsigned m = __ballot_sync(0xffffffffu, conflict);
                if (m == 0u) {
                    if (lane == 0) {
                        s_sel[nsel] = cb;
                        float* o = pred + nsel * 6;
                        o[0] = fminf(fmaxf(cb.x, 0.0f), 1.0f);
                        o[1] = fminf(fmaxf(cb.y, 0.0f), 1.0f);
                        o[2] = fminf(fmaxf(cb.z, 0.0f), 1.0f);
                        o[3] = fminf(fmaxf(cb.w, 0.0f), 1.0f);
                        o[4] = s_cs[j];
                        o[5] = 0.0f;
                    }
                    __syncwarp();
                    nsel++;
                }
            }
            if (lane == 0) s_nsel = nsel;
        }
        __syncthreads();
        nsel = s_nsel;
        if (nsel >= MAXB) break;
    }

    __syncthreads();
    // valid counts appended after the [B,100,6] pred block (written as values)
    if (tid == 0 && out_size >= BATCH * MAXB * 6 + BATCH) {
        out[BATCH * MAXB * 6 + b] = (float)s_nsel;
    }
}

// ---------------------------------------------------------------------------
extern "C" void kernel_launch(void* const* d_in, const int* in_sizes, int n_in,
                              void* d_out, int out_size) {
    const float* bbox = (const float*)d_in[0];   // [32,25200,4]
    const float* p    = (const float*)d_in[1];   // [32,25200,1]
    const float* c    = (const float*)d_in[2];   // [32,25200,80]
    float* out = (float*)d_out;

    float* scores;
    cudaGetSymbolAddress((void**)&scores, g_scores);

    const int total = BATCH * NBOX;
    score_kernel<<<(total + 255) / 256, 256>>>(p, c, scores);
    nms_kernel<<<BATCH, 1024>>>(bbox, scores, out, out_size);
}